// round 6
// baseline (speedup 1.0000x reference)
#include <cuda_runtime.h>
#include <math.h>
#include <stdint.h>

// Problem constants
#define NODESG   116
#define HEADS    2
#define DHEAD    116
#define HIDD     256
#define BGRAPH   512
#define NTOT     (BGRAPH * NODESG)      // 59392
#define DEG      8
#define DOUT     232
#define PSTRIDE  1024                   // padded fused output width (q|k|v|s|pad)
#define NPACK    928                    // valid columns (4*232)

// GEMM tiling
#define BM 128
#define BN 128
#define BK 32
#define ASTRIDE 40                       // padded row stride in words (64-bit conflict-free)
#define STG_W   (BM * ASTRIDE)           // words per operand stage = 5120
#define GEMM_SMEM (4 * STG_W * 4)        // A0,B0,A1,B1 = 81920 B

// Scratch (device globals: no allocation allowed)
__device__ uint32_t d_At[(size_t)NTOT * HIDD];                // A as tf32 bits, k-permuted
__device__ uint32_t d_Wt[PSTRIDE * HIDD];                     // W^T padded tf32 bits, k-permuted
__device__ float d_P[(size_t)NTOT * PSTRIDE];                 // fused projections
__device__ float d_HP[(size_t)NTOT * DOUT];                   // h_proj
__device__ float d_E[NTOT];                                   // per-node mean
__device__ int   d_is32;                                      // edge_index dtype flag

// k-permutation within 8-group: position p holds source j = (p&1)? p/2+4 : p/2
__device__ __forceinline__ int kperm_src(int p) {
    return (p & 1) ? (p >> 1) + 4 : (p >> 1);
}

// ---------------------------------------------------------------------------
// helpers
// ---------------------------------------------------------------------------
__device__ __forceinline__ uint32_t f2tf32(float x) {
    uint32_t r;
    asm("cvt.rna.tf32.f32 %0, %1;" : "=r"(r) : "f"(x));
    return r;
}
__device__ __forceinline__ void mma16n8k8(float* c, const uint32_t* a, const uint32_t* b) {
    asm volatile(
        "mma.sync.aligned.m16n8k8.row.col.f32.tf32.tf32.f32 "
        "{%0,%1,%2,%3},{%4,%5,%6,%7},{%8,%9},{%0,%1,%2,%3};"
        : "+f"(c[0]), "+f"(c[1]), "+f"(c[2]), "+f"(c[3])
        : "r"(a[0]), "r"(a[1]), "r"(a[2]), "r"(a[3]), "r"(b[0]), "r"(b[1]));
}
__device__ __forceinline__ uint32_t smem_u32(const void* p) {
    uint32_t a;
    asm("{ .reg .u64 t; cvta.to.shared.u64 t, %1; cvt.u32.u64 %0, t; }" : "=r"(a) : "l"(p));
    return a;
}
__device__ __forceinline__ void cp16(uint32_t dst, const void* src) {
    asm volatile("cp.async.cg.shared.global [%0], [%1], 16;" :: "r"(dst), "l"(src));
}

// ---------------------------------------------------------------------------
// 0) edge_index dtype detection: int64 little-endian => all odd int32 words 0
// ---------------------------------------------------------------------------
__global__ void detect_kernel(const int* __restrict__ ei) {
    int j = blockIdx.x * blockDim.x + threadIdx.x;
    if (j < 4096) {
        if (ei[2 * j + 1] != 0) atomicOr(&d_is32, 1);
    }
}

// ---------------------------------------------------------------------------
// 1a) A prep: tf32-convert + k-permute h into d_At
// ---------------------------------------------------------------------------
__global__ __launch_bounds__(256) void aprep_kernel(const float* __restrict__ h) {
    int idx = blockIdx.x * blockDim.x + threadIdx.x;
    if (idx >= NTOT * HIDD) return;
    int row = idx >> 8;
    int p   = idx & 255;
    int k   = (p & ~7) | kperm_src(p & 7);
    d_At[idx] = f2tf32(h[(size_t)row * HIDD + k]);
}

// ---------------------------------------------------------------------------
// 1b) pack W^T as tf32 bits, k-permuted: d_Wt[n][k'], zero-padded n >= 928
// ---------------------------------------------------------------------------
__global__ __launch_bounds__(256) void pack_kernel(
        const float* __restrict__ Wq, const float* __restrict__ Wk,
        const float* __restrict__ Wv, const float* __restrict__ Ws) {
    int idx = blockIdx.x * blockDim.x + threadIdx.x;   // n*256 + k'
    if (idx >= PSTRIDE * HIDD) return;
    int n = idx >> 8;
    int p = idx & 255;
    int k = (p & ~7) | kperm_src(p & 7);
    float v = 0.0f;
    if      (n < 232) v = Wq[k * 232 + n];
    else if (n < 464) v = Wk[k * 232 + (n - 232)];
    else if (n < 696) v = Wv[k * 232 + (n - 464)];
    else if (n < 928) v = Ws[k * 232 + (n - 696)];
    d_Wt[idx] = f2tf32(v);
}

// ---------------------------------------------------------------------------
// 2) tf32 mma.sync GEMM: P[N,1024] = h[N,256] @ W[256,1024]
//    CTA 128x128, BK=32, 256 threads, warp tile 64x32, cp.async double buffer.
//    Both operands pre-converted tf32 bits, k-permuted -> fragment LDS.64 only.
// ---------------------------------------------------------------------------
__global__ __launch_bounds__(256, 2) void gemm_mma_kernel() {
    extern __shared__ uint32_t sm[];
    int tid  = threadIdx.x;
    int lane = tid & 31;
    int warp = tid >> 5;
    int wr = warp >> 2;          // 0..1 (M)
    int wc = warp & 3;           // 0..3 (N)
    int gid = lane >> 2;         // 0..7
    int tig = lane & 3;          // 0..3
    int brow = blockIdx.y * BM;
    int bcol = blockIdx.x * BN;

    const uint32_t* Ag = d_At + (size_t)brow * HIDD;
    const uint32_t* Bg = d_Wt + (size_t)bcol * HIDD;

    uint32_t sbase = smem_u32(sm);
    int r  = tid >> 3;           // 0..31 -> +t*32 rows
    int c4 = tid & 7;            // 16B index within 32-word row

    float c[4][4][4];
#pragma unroll
    for (int mt = 0; mt < 4; mt++)
#pragma unroll
        for (int nt = 0; nt < 4; nt++)
#pragma unroll
            for (int q = 0; q < 4; q++) c[mt][nt][q] = 0.0f;

    // prologue: stage 0
    {
#pragma unroll
        for (int t = 0; t < 4; t++) {
            int rr = r + t * 32;
            uint32_t soff = (uint32_t)(rr * ASTRIDE + c4 * 4) * 4;
            cp16(sbase + soff, Ag + (size_t)rr * HIDD + c4 * 4);
            cp16(sbase + STG_W * 4 + soff, Bg + (size_t)rr * HIDD + c4 * 4);
        }
        asm volatile("cp.async.commit_group;");
    }

    for (int ch = 0; ch < HIDD / BK; ch++) {
        if (ch < HIDD / BK - 1) {
            int kc0 = (ch + 1) * BK;
            uint32_t stg = ((ch + 1) & 1) ? 2u * STG_W * 4u : 0u;
#pragma unroll
            for (int t = 0; t < 4; t++) {
                int rr = r + t * 32;
                uint32_t soff = (uint32_t)(rr * ASTRIDE + c4 * 4) * 4;
                cp16(sbase + stg + soff, Ag + (size_t)rr * HIDD + kc0 + c4 * 4);
                cp16(sbase + stg + STG_W * 4 + soff, Bg + (size_t)rr * HIDD + kc0 + c4 * 4);
            }
            asm volatile("cp.async.commit_group;");
            asm volatile("cp.async.wait_group 1;");
        } else {
            asm volatile("cp.async.wait_group 0;");
        }
        __syncthreads();

        const uint32_t* As = sm + (ch & 1) * 2 * STG_W;
        const uint32_t* Bs = As + STG_W;

#pragma unroll
        for (int ks = 0; ks < 4; ks++) {
            // A fragments: 2 x LDS.64 per m-tile; pair = (k=tig, k=tig+4)
            uint32_t af[4][4];
#pragma unroll
            for (int mt = 0; mt < 4; mt++) {
                int r0 = wr * 64 + mt * 16 + gid;
                const uint2* pa = (const uint2*)(As + r0 * ASTRIDE + ks * 8 + 2 * tig);
                const uint2* pb = (const uint2*)(As + (r0 + 8) * ASTRIDE + ks * 8 + 2 * tig);
                uint2 ua = *pa, ub = *pb;
                af[mt][0] = ua.x; af[mt][2] = ua.y;
                af[mt][1] = ub.x; af[mt][3] = ub.y;
            }
            // B fragments: 1 x LDS.64 per n-tile
            uint32_t bf[4][2];
#pragma unroll
            for (int nt = 0; nt < 4; nt++) {
                int n0 = wc * 32 + nt * 8 + gid;
                uint2 ub = *(const uint2*)(Bs + n0 * ASTRIDE + ks * 8 + 2 * tig);
                bf[nt][0] = ub.x; bf[nt][1] = ub.y;
            }
#pragma unroll
            for (int mt = 0; mt < 4; mt++)
#pragma unroll
                for (int nt = 0; nt < 4; nt++)
                    mma16n8k8(c[mt][nt], af[mt], bf[nt]);
        }
        __syncthreads();
    }

    // Epilogue: direct store to d_P, skip padded columns >= 928
#pragma unroll
    for (int mt = 0; mt < 4; mt++) {
        int r0 = brow + wr * 64 + mt * 16 + gid;
#pragma unroll
        for (int nt = 0; nt < 4; nt++) {
            int gc = bcol + wc * 32 + nt * 8 + tig * 2;
            if (gc < NPACK) {
                float* p = d_P + (size_t)r0 * PSTRIDE + gc;
                *(float2*)p = make_float2(c[mt][nt][0], c[mt][nt][1]);
                *(float2*)(p + 8 * PSTRIDE) = make_float2(c[mt][nt][2], c[mt][nt][3]);
            }
        }
    }
}

// ---------------------------------------------------------------------------
// 3) warp-per-node edge attention + skip + per-node mean
// ---------------------------------------------------------------------------
__global__ __launch_bounds__(256) void attn_kernel(const int* __restrict__ esrc) {
    int warp = (blockIdx.x * blockDim.x + threadIdx.x) >> 5;
    int lane = threadIdx.x & 31;
    if (warp >= NTOT) return;
    int i = warp;
    int is32 = d_is32;

    const float* Pq = d_P + (size_t)i * PSTRIDE;

    float q[8];
#pragma unroll
    for (int j = 0; j < 8; j++) {
        int idx = lane + 32 * j;
        q[j] = (idx < DOUT) ? Pq[idx] : 0.0f;
    }

    int myedge = 0;
    if (lane < DEG) {
        int e = i * DEG + lane;
        myedge = is32 ? esrc[e] : esrc[2 * e];   // int64: low word
    }
    int srcs[DEG];
#pragma unroll
    for (int e = 0; e < DEG; e++) srcs[e] = __shfl_sync(0xffffffffu, myedge, e);

    const float scale = 0.09284766908852593f;    // 1/sqrt(116)
    float s0[DEG], s1[DEG];
#pragma unroll
    for (int e = 0; e < DEG; e++) {
        const float* Kp = d_P + (size_t)srcs[e] * PSTRIDE + 232;
        float a0 = 0.0f, a1 = 0.0f;
#pragma unroll
        for (int j = 0; j < 8; j++) {
            int idx = lane + 32 * j;
            if (idx < DOUT) {
                float prod = q[j] * Kp[idx];
                if (idx < DHEAD) a0 += prod; else a1 += prod;
            }
        }
#pragma unroll
        for (int off = 16; off > 0; off >>= 1) {
            a0 += __shfl_xor_sync(0xffffffffu, a0, off);
            a1 += __shfl_xor_sync(0xffffffffu, a1, off);
        }
        s0[e] = a0 * scale;
        s1[e] = a1 * scale;
    }

    float m0 = s0[0], m1 = s1[0];
#pragma unroll
    for (int e = 1; e < DEG; e++) { m0 = fmaxf(m0, s0[e]); m1 = fmaxf(m1, s1[e]); }
    float ex0[DEG], ex1[DEG], den0 = 0.0f, den1 = 0.0f;
#pragma unroll
    for (int e = 0; e < DEG; e++) {
        ex0[e] = __expf(s0[e] - m0);
        ex1[e] = __expf(s1[e] - m1);
        den0 += ex0[e]; den1 += ex1[e];
    }
    float r0 = 1.0f / (den0 + 1e-16f);
    float r1 = 1.0f / (den1 + 1e-16f);
    float al0[DEG], al1[DEG];
#pragma unroll
    for (int e = 0; e < DEG; e++) { al0[e] = ex0[e] * r0; al1[e] = ex1[e] * r1; }

    float o[8];
#pragma unroll
    for (int j = 0; j < 8; j++) o[j] = 0.0f;
#pragma unroll
    for (int e = 0; e < DEG; e++) {
        const float* Vp = d_P + (size_t)srcs[e] * PSTRIDE + 464;
#pragma unroll
        for (int j = 0; j < 8; j++) {
            int idx = lane + 32 * j;
            if (idx < DOUT) {
                float a = (idx < DHEAD) ? al0[e] : al1[e];
                o[j] += a * Vp[idx];
            }
        }
    }
    const float* Sp = d_P + (size_t)i * PSTRIDE + 696;
#pragma unroll
    for (int j = 0; j < 8; j++) {
        int idx = lane + 32 * j;
        if (idx < DOUT) o[j] += Sp[idx];
    }

    float psum = 0.0f;
#pragma unroll
    for (int j = 0; j < 8; j++) psum += o[j];
#pragma unroll
    for (int off = 16; off > 0; off >>= 1) psum += __shfl_xor_sync(0xffffffffu, psum, off);
    if (lane == 0) d_E[i] = psum * (1.0f / (float)DOUT);

    float* HPp = d_HP + (size_t)i * DOUT;
#pragma unroll
    for (int j = 0; j < 8; j++) {
        int idx = lane + 32 * j;
        if (idx < DOUT) HPp[idx] = o[j];
    }
}

// ---------------------------------------------------------------------------
// 4) per-graph softmax over nodes + weighted output; writes d_out directly
// ---------------------------------------------------------------------------
__global__ __launch_bounds__(128) void finalize_kernel(float* __restrict__ out) {
    __shared__ float sh[128];
    __shared__ float alpha_sh[NODESG];
    int g = blockIdx.x;
    int tid = threadIdx.x;

    float ev = (tid < NODESG) ? d_E[g * NODESG + tid] : -3.4e38f;
    sh[tid] = ev;
    __syncthreads();
#pragma unroll
    for (int s = 64; s > 0; s >>= 1) {
        if (tid < s) sh[tid] = fmaxf(sh[tid], sh[tid + s]);
        __syncthreads();
    }
    float m = sh[0];
    __syncthreads();

    float ex = (tid < NODESG) ? __expf(ev - m) : 0.0f;
    sh[tid] = ex;
    __syncthreads();
#pragma unroll
    for (int s = 64; s > 0; s >>= 1) {
        if (tid < s) sh[tid] += sh[tid + s];
        __syncthreads();
    }
    float inv = 1.0f / sh[0];

    float a = ex * inv;
    if (tid < NODESG) {
        out[g * NODESG + tid] = a;
        alpha_sh[tid] = a;
    }
    __syncthreads();

    const float* src = d_HP + (size_t)g * (NODESG * DOUT);
    float*       dst = out + NTOT + (size_t)g * (NODESG * DOUT);
    for (int idx = tid; idx < NODESG * DOUT; idx += 128) {
        dst[idx] = alpha_sh[idx / DOUT] * src[idx];
    }
}

// ---------------------------------------------------------------------------
extern "C" void kernel_launch(void* const* d_in, const int* in_sizes, int n_in,
                              void* d_out, int out_size) {
    const float* h  = (const float*)d_in[0];
    const int*   ei = (const int*)d_in[1];
    // d_in[2] = batch_index (unused: batch = i / 116 by construction)
    const float* Wq = (const float*)d_in[3];
    const float* Wk = (const float*)d_in[4];
    const float* Wv = (const float*)d_in[5];
    const float* Ws = (const float*)d_in[6];
    float* out = (float*)d_out;

    cudaFuncSetAttribute(gemm_mma_kernel,
                         cudaFuncAttributeMaxDynamicSharedMemorySize, GEMM_SMEM);

    void* flag_ptr = nullptr;
    cudaGetSymbolAddress(&flag_ptr, d_is32);
    cudaMemsetAsync(flag_ptr, 0, sizeof(int));

    detect_kernel<<<16, 256>>>(ei);
    pack_kernel<<<(PSTRIDE * HIDD + 255) / 256, 256>>>(Wq, Wk, Wv, Ws);
    aprep_kernel<<<(NTOT * HIDD + 255) / 256, 256>>>(h);

    dim3 gg(PSTRIDE / BN, NTOT / BM);   // x=8 (ncol, fastest -> A reuse), y=464
    gemm_mma_kernel<<<gg, 256, GEMM_SMEM>>>();

    attn_kernel<<<NTOT / 8, 256>>>(ei);

    finalize_kernel<<<BGRAPH, 128>>>(out);
}

// round 7
// speedup vs baseline: 1.4614x; 1.4614x over previous
#include <cuda_runtime.h>
#include <cuda_fp16.h>
#include <math.h>
#include <stdint.h>

// Problem constants
#define NODESG   116
#define HEADS    2
#define DHEAD    116
#define HIDD     256
#define BGRAPH   512
#define NTOT     (BGRAPH * NODESG)      // 59392
#define DEG      8
#define DOUT     232
#define PSTRIDE  1024                   // padded fused output width (q|k|v|s|pad)
#define NPACK    928                    // valid columns (4*232)

// GEMM tiling
#define BM 128
#define BN 128
#define BK 32
#define RSH 48                           // smem row stride in halves (96 B, conflict-free)
#define STG_B (BM * RSH * 2)             // bytes per operand stage = 12288
#define GEMM_SMEM (4 * STG_B)            // A0,B0,A1,B1 = 49152 B

// Scratch (device globals: no allocation allowed)
__device__ __half d_Ah[(size_t)NTOT * HIDD];                  // A fp16, k-permuted
__device__ __half d_Wh[PSTRIDE * HIDD];                       // W^T padded fp16, k-permuted
__device__ float d_P[(size_t)NTOT * PSTRIDE];                 // fused projections
__device__ float d_HP[(size_t)NTOT * DOUT];                   // h_proj
__device__ float d_E[NTOT];                                   // per-node mean
__device__ int   d_is32;                                      // edge_index dtype flag

// k-permutation within 16-group (pair granularity):
// stored pair q (0..7) holds source k-pair base: j=q>>1; odd q -> 2j+8, even -> 2j
__device__ __forceinline__ int kpair_src(int q) {
    int j = q >> 1;
    return (q & 1) ? (2 * j + 8) : (2 * j);
}

// ---------------------------------------------------------------------------
// helpers
// ---------------------------------------------------------------------------
__device__ __forceinline__ void mma16816(float* c, const uint32_t* a, const uint32_t* b) {
    asm volatile(
        "mma.sync.aligned.m16n8k16.row.col.f32.f16.f16.f32 "
        "{%0,%1,%2,%3},{%4,%5,%6,%7},{%8,%9},{%0,%1,%2,%3};"
        : "+f"(c[0]), "+f"(c[1]), "+f"(c[2]), "+f"(c[3])
        : "r"(a[0]), "r"(a[1]), "r"(a[2]), "r"(a[3]), "r"(b[0]), "r"(b[1]));
}
__device__ __forceinline__ uint32_t smem_u32(const void* p) {
    uint32_t a;
    asm("{ .reg .u64 t; cvta.to.shared.u64 t, %1; cvt.u32.u64 %0, t; }" : "=r"(a) : "l"(p));
    return a;
}
__device__ __forceinline__ void cp16(uint32_t dst, const void* src) {
    asm volatile("cp.async.cg.shared.global [%0], [%1], 16;" :: "r"(dst), "l"(src));
}

// ---------------------------------------------------------------------------
// 0) edge_index dtype detection: int64 little-endian => all odd int32 words 0
// ---------------------------------------------------------------------------
__global__ void detect_kernel(const int* __restrict__ ei) {
    int j = blockIdx.x * blockDim.x + threadIdx.x;
    if (j < 4096) {
        if (ei[2 * j + 1] != 0) atomicOr(&d_is32, 1);
    }
}

// ---------------------------------------------------------------------------
// 1a) A prep: fp16-convert + k-permute h into d_Ah (pair-wise, 4B writes)
// ---------------------------------------------------------------------------
__global__ __launch_bounds__(256) void aprep_kernel(const float* __restrict__ h) {
    int pi = blockIdx.x * blockDim.x + threadIdx.x;    // pair index
    if (pi >= NTOT * HIDD / 2) return;
    int row = pi >> 7;
    int q   = pi & 127;                                 // pair within row
    int k   = (q & ~7) * 2 + kpair_src(q & 7);          // source k (pair base)
    const float* src = h + (size_t)row * HIDD + k;
    __half2 v = __floats2half2_rn(src[0], src[1]);
    ((__half2*)d_Ah)[pi] = v;
}

// ---------------------------------------------------------------------------
// 1b) pack W^T fp16, k-permuted: d_Wh[n][k'], zero-padded n >= 928
// ---------------------------------------------------------------------------
__global__ __launch_bounds__(256) void pack_kernel(
        const float* __restrict__ Wq, const float* __restrict__ Wk,
        const float* __restrict__ Wv, const float* __restrict__ Ws) {
    int pi = blockIdx.x * blockDim.x + threadIdx.x;    // pair index
    if (pi >= PSTRIDE * HIDD / 2) return;
    int n = pi >> 7;
    int q = pi & 127;
    int k = (q & ~7) * 2 + kpair_src(q & 7);
    float v0 = 0.0f, v1 = 0.0f;
    if      (n < 232) { v0 = Wq[k * 232 + n];       v1 = Wq[(k + 1) * 232 + n]; }
    else if (n < 464) { v0 = Wk[k * 232 + n - 232]; v1 = Wk[(k + 1) * 232 + n - 232]; }
    else if (n < 696) { v0 = Wv[k * 232 + n - 464]; v1 = Wv[(k + 1) * 232 + n - 464]; }
    else if (n < 928) { v0 = Ws[k * 232 + n - 696]; v1 = Ws[(k + 1) * 232 + n - 696]; }
    ((__half2*)d_Wh)[pi] = __floats2half2_rn(v0, v1);
}

// ---------------------------------------------------------------------------
// 2) fp16 mma.sync GEMM: P[N,1024] = h[N,256] @ W[256,1024]
//    CTA 128x128, BK=32 (2 k16 steps), 256 threads, warp tile 64x32,
//    cp.async double buffer, fragment loads = LDS.64 only.
// ---------------------------------------------------------------------------
__global__ __launch_bounds__(256, 2) void gemm_mma_kernel() {
    extern __shared__ __align__(16) char sm[];
    int tid  = threadIdx.x;
    int lane = tid & 31;
    int warp = tid >> 5;
    int wr = warp >> 2;          // 0..1 (M)
    int wc = warp & 3;           // 0..3 (N)
    int gid = lane >> 2;         // 0..7
    int tig = lane & 3;          // 0..3
    int brow = blockIdx.y * BM;
    int bcol = blockIdx.x * BN;

    const __half* Ag = d_Ah + (size_t)brow * HIDD;
    const __half* Bg = d_Wh + (size_t)bcol * HIDD;

    uint32_t sbase = smem_u32(sm);
    // cp.async mapping: 512 x 16B per operand per chunk, 2 per thread
    int rr0 = tid >> 2;          // 0..63 (+64 for second)
    int cc  = tid & 3;           // 16B unit within 64B row

    float c[4][4][4];
#pragma unroll
    for (int mt = 0; mt < 4; mt++)
#pragma unroll
        for (int nt = 0; nt < 4; nt++)
#pragma unroll
            for (int q = 0; q < 4; q++) c[mt][nt][q] = 0.0f;

    auto stage_in = [&](int ch) {
        uint32_t stg = sbase + (ch & 1) * 2 * STG_B;
        int kc0 = ch * BK;
#pragma unroll
        for (int t = 0; t < 2; t++) {
            int rr = rr0 + t * 64;
            uint32_t soff = (uint32_t)(rr * (RSH * 2) + cc * 16);
            cp16(stg + soff, Ag + (size_t)rr * HIDD + kc0 + cc * 8);
            cp16(stg + STG_B + soff, Bg + (size_t)rr * HIDD + kc0 + cc * 8);
        }
        asm volatile("cp.async.commit_group;");
    };

    stage_in(0);

    for (int ch = 0; ch < HIDD / BK; ch++) {
        if (ch < HIDD / BK - 1) {
            stage_in(ch + 1);
            asm volatile("cp.async.wait_group 1;");
        } else {
            asm volatile("cp.async.wait_group 0;");
        }
        __syncthreads();

        const char* As = sm + (ch & 1) * 2 * STG_B;
        const char* Bs = As + STG_B;

#pragma unroll
        for (int ks = 0; ks < 2; ks++) {
            uint32_t af[4][4];
#pragma unroll
            for (int mt = 0; mt < 4; mt++) {
                int r0 = wr * 64 + mt * 16 + gid;
                uint2 ua = *(const uint2*)(As + r0 * (RSH * 2) + ks * 32 + tig * 8);
                uint2 ub = *(const uint2*)(As + (r0 + 8) * (RSH * 2) + ks * 32 + tig * 8);
                af[mt][0] = ua.x; af[mt][2] = ua.y;    // row gid:   (a0, a2)
                af[mt][1] = ub.x; af[mt][3] = ub.y;    // row gid+8: (a1, a3)
            }
            uint32_t bf[4][2];
#pragma unroll
            for (int nt = 0; nt < 4; nt++) {
                int n0 = wc * 32 + nt * 8 + gid;
                uint2 ub = *(const uint2*)(Bs + n0 * (RSH * 2) + ks * 32 + tig * 8);
                bf[nt][0] = ub.x; bf[nt][1] = ub.y;    // (b0, b1)
            }
#pragma unroll
            for (int mt = 0; mt < 4; mt++)
#pragma unroll
                for (int nt = 0; nt < 4; nt++)
                    mma16816(c[mt][nt], af[mt], bf[nt]);
        }
        __syncthreads();
    }

    // Epilogue: direct store to d_P, skip padded columns >= 928
#pragma unroll
    for (int mt = 0; mt < 4; mt++) {
        int r0 = brow + wr * 64 + mt * 16 + gid;
#pragma unroll
        for (int nt = 0; nt < 4; nt++) {
            int gc = bcol + wc * 32 + nt * 8 + tig * 2;
            if (gc < NPACK) {
                float* p = d_P + (size_t)r0 * PSTRIDE + gc;
                *(float2*)p = make_float2(c[mt][nt][0], c[mt][nt][1]);
                *(float2*)(p + 8 * PSTRIDE) = make_float2(c[mt][nt][2], c[mt][nt][3]);
            }
        }
    }
}

// ---------------------------------------------------------------------------
// 3) warp-per-node edge attention + skip + per-node mean
// ---------------------------------------------------------------------------
__global__ __launch_bounds__(256) void attn_kernel(const int* __restrict__ esrc) {
    int warp = (blockIdx.x * blockDim.x + threadIdx.x) >> 5;
    int lane = threadIdx.x & 31;
    if (warp >= NTOT) return;
    int i = warp;
    int is32 = d_is32;

    const float* Pq = d_P + (size_t)i * PSTRIDE;

    float q[8];
#pragma unroll
    for (int j = 0; j < 8; j++) {
        int idx = lane + 32 * j;
        q[j] = (idx < DOUT) ? Pq[idx] : 0.0f;
    }

    int myedge = 0;
    if (lane < DEG) {
        int e = i * DEG + lane;
        myedge = is32 ? esrc[e] : esrc[2 * e];   // int64: low word
    }
    int srcs[DEG];
#pragma unroll
    for (int e = 0; e < DEG; e++) srcs[e] = __shfl_sync(0xffffffffu, myedge, e);

    const float scale = 0.09284766908852593f;    // 1/sqrt(116)
    float s0[DEG], s1[DEG];
#pragma unroll
    for (int e = 0; e < DEG; e++) {
        const float* Kp = d_P + (size_t)srcs[e] * PSTRIDE + 232;
        float a0 = 0.0f, a1 = 0.0f;
#pragma unroll
        for (int j = 0; j < 8; j++) {
            int idx = lane + 32 * j;
            if (idx < DOUT) {
                float prod = q[j] * Kp[idx];
                if (idx < DHEAD) a0 += prod; else a1 += prod;
            }
        }
#pragma unroll
        for (int off = 16; off > 0; off >>= 1) {
            a0 += __shfl_xor_sync(0xffffffffu, a0, off);
            a1 += __shfl_xor_sync(0xffffffffu, a1, off);
        }
        s0[e] = a0 * scale;
        s1[e] = a1 * scale;
    }

    float m0 = s0[0], m1 = s1[0];
#pragma unroll
    for (int e = 1; e < DEG; e++) { m0 = fmaxf(m0, s0[e]); m1 = fmaxf(m1, s1[e]); }
    float ex0[DEG], ex1[DEG], den0 = 0.0f, den1 = 0.0f;
#pragma unroll
    for (int e = 0; e < DEG; e++) {
        ex0[e] = __expf(s0[e] - m0);
        ex1[e] = __expf(s1[e] - m1);
        den0 += ex0[e]; den1 += ex1[e];
    }
    float r0 = 1.0f / (den0 + 1e-16f);
    float r1 = 1.0f / (den1 + 1e-16f);
    float al0[DEG], al1[DEG];
#pragma unroll
    for (int e = 0; e < DEG; e++) { al0[e] = ex0[e] * r0; al1[e] = ex1[e] * r1; }

    float o[8];
#pragma unroll
    for (int j = 0; j < 8; j++) o[j] = 0.0f;
#pragma unroll
    for (int e = 0; e < DEG; e++) {
        const float* Vp = d_P + (size_t)srcs[e] * PSTRIDE + 464;
#pragma unroll
        for (int j = 0; j < 8; j++) {
            int idx = lane + 32 * j;
            if (idx < DOUT) {
                float a = (idx < DHEAD) ? al0[e] : al1[e];
                o[j] += a * Vp[idx];
            }
        }
    }
    const float* Sp = d_P + (size_t)i * PSTRIDE + 696;
#pragma unroll
    for (int j = 0; j < 8; j++) {
        int idx = lane + 32 * j;
        if (idx < DOUT) o[j] += Sp[idx];
    }

    float psum = 0.0f;
#pragma unroll
    for (int j = 0; j < 8; j++) psum += o[j];
#pragma unroll
    for (int off = 16; off > 0; off >>= 1) psum += __shfl_xor_sync(0xffffffffu, psum, off);
    if (lane == 0) d_E[i] = psum * (1.0f / (float)DOUT);

    float* HPp = d_HP + (size_t)i * DOUT;
#pragma unroll
    for (int j = 0; j < 8; j++) {
        int idx = lane + 32 * j;
        if (idx < DOUT) HPp[idx] = o[j];
    }
}

// ---------------------------------------------------------------------------
// 4) per-graph softmax over nodes + weighted output; writes d_out directly
// ---------------------------------------------------------------------------
__global__ __launch_bounds__(256) void finalize_kernel(float* __restrict__ out) {
    __shared__ float sh[128];
    __shared__ float alpha_sh[NODESG];
    int g = blockIdx.x;
    int tid = threadIdx.x;

    if (tid < 128) {
        float ev = (tid < NODESG) ? d_E[g * NODESG + tid] : -3.4e38f;
        sh[tid] = ev;
    }
    __syncthreads();
#pragma unroll
    for (int s = 64; s > 0; s >>= 1) {
        if (tid < s) sh[tid] = fmaxf(sh[tid], sh[tid + s]);
        __syncthreads();
    }
    float m = sh[0];
    __syncthreads();

    float ev = (tid < NODESG) ? d_E[g * NODESG + tid] : 0.0f;
    float ex = (tid < NODESG) ? __expf(ev - m) : 0.0f;
    if (tid < 128) sh[tid] = ex;
    __syncthreads();
#pragma unroll
    for (int s = 64; s > 0; s >>= 1) {
        if (tid < s) sh[tid] += sh[tid + s];
        __syncthreads();
    }
    float inv = 1.0f / sh[0];

    if (tid < NODESG) {
        float a = ex * inv;
        out[g * NODESG + tid] = a;
        alpha_sh[tid] = a;
    }
    __syncthreads();

    const float* src = d_HP + (size_t)g * (NODESG * DOUT);
    float*       dst = out + NTOT + (size_t)g * (NODESG * DOUT);
    if (tid < DOUT) {
#pragma unroll 4
        for (int n = 0; n < NODESG; n++) {
            dst[n * DOUT + tid] = alpha_sh[n] * src[n * DOUT + tid];
        }
    }
}

// ---------------------------------------------------------------------------
extern "C" void kernel_launch(void* const* d_in, const int* in_sizes, int n_in,
                              void* d_out, int out_size) {
    const float* h  = (const float*)d_in[0];
    const int*   ei = (const int*)d_in[1];
    // d_in[2] = batch_index (unused: batch = i / 116 by construction)
    const float* Wq = (const float*)d_in[3];
    const float* Wk = (const float*)d_in[4];
    const float* Wv = (const float*)d_in[5];
    const float* Ws = (const float*)d_in[6];
    float* out = (float*)d_out;

    cudaFuncSetAttribute(gemm_mma_kernel,
                         cudaFuncAttributeMaxDynamicSharedMemorySize, GEMM_SMEM);

    void* flag_ptr = nullptr;
    cudaGetSymbolAddress(&flag_ptr, d_is32);
    cudaMemsetAsync(flag_ptr, 0, sizeof(int));

    detect_kernel<<<16, 256>>>(ei);
    pack_kernel<<<(PSTRIDE * HIDD / 2 + 255) / 256, 256>>>(Wq, Wk, Wv, Ws);
    aprep_kernel<<<(NTOT * HIDD / 2 + 255) / 256, 256>>>(h);

    dim3 gg(PSTRIDE / BN, NTOT / BM);   // x=8 (ncol, fastest -> A reuse), y=464
    gemm_mma_kernel<<<gg, 256, GEMM_SMEM>>>();

    attn_kernel<<<NTOT / 8, 256>>>(ei);

    finalize_kernel<<<BGRAPH, 256>>>(out);
}

// round 8
// speedup vs baseline: 1.5862x; 1.0854x over previous
#include <cuda_runtime.h>
#include <cuda_fp16.h>
#include <math.h>
#include <stdint.h>

// Problem constants
#define NODESG   116
#define HEADS    2
#define DHEAD    116
#define HIDD     256
#define BGRAPH   512
#define NTOT     (BGRAPH * NODESG)      // 59392
#define DEG      8
#define DOUT     232
#define PSTRIDE  1024                   // padded fused output width (q|k|v|s|pad)
#define NPACK    928                    // valid columns (4*232)
#define NPAIR    116                    // half2 pairs per 232-col section
#define HPAIR    58                     // pairs in head 0

// GEMM tiling
#define BM 128
#define BN 128
#define BK 32
#define RSH 48                           // smem row stride in halves (96 B, conflict-free)
#define STG_B (BM * RSH * 2)             // bytes per operand stage = 12288
#define GEMM_SMEM (4 * STG_B)            // A0,B0,A1,B1 = 49152 B

// Scratch (device globals: no allocation allowed)
__device__ __half d_Ah[(size_t)NTOT * HIDD];                  // A fp16, k-permuted
__device__ __half d_Wh[PSTRIDE * HIDD];                       // W^T padded fp16, k-permuted
__device__ __half d_Ph[(size_t)NTOT * PSTRIDE];               // fused projections (fp16)
__device__ float d_HP[(size_t)NTOT * DOUT];                   // h_proj
__device__ float d_E[NTOT];                                   // per-node mean
__device__ int   d_is32;                                      // edge_index dtype flag

// k-permutation within 16-group (pair granularity):
// stored pair q (0..7) holds source k-pair base: j=q>>1; odd q -> 2j+8, even -> 2j
__device__ __forceinline__ int kpair_src(int q) {
    int j = q >> 1;
    return (q & 1) ? (2 * j + 8) : (2 * j);
}

// ---------------------------------------------------------------------------
// helpers
// ---------------------------------------------------------------------------
__device__ __forceinline__ void mma16816(float* c, const uint32_t* a, const uint32_t* b) {
    asm volatile(
        "mma.sync.aligned.m16n8k16.row.col.f32.f16.f16.f32 "
        "{%0,%1,%2,%3},{%4,%5,%6,%7},{%8,%9},{%0,%1,%2,%3};"
        : "+f"(c[0]), "+f"(c[1]), "+f"(c[2]), "+f"(c[3])
        : "r"(a[0]), "r"(a[1]), "r"(a[2]), "r"(a[3]), "r"(b[0]), "r"(b[1]));
}
__device__ __forceinline__ uint32_t smem_u32(const void* p) {
    uint32_t a;
    asm("{ .reg .u64 t; cvta.to.shared.u64 t, %1; cvt.u32.u64 %0, t; }" : "=r"(a) : "l"(p));
    return a;
}
__device__ __forceinline__ void cp16(uint32_t dst, const void* src) {
    asm volatile("cp.async.cg.shared.global [%0], [%1], 16;" :: "r"(dst), "l"(src));
}

// ---------------------------------------------------------------------------
// 0) edge_index dtype detection: int64 little-endian => all odd int32 words 0
// ---------------------------------------------------------------------------
__global__ void detect_kernel(const int* __restrict__ ei) {
    int j = blockIdx.x * blockDim.x + threadIdx.x;
    if (j < 4096) {
        if (ei[2 * j + 1] != 0) atomicOr(&d_is32, 1);
    }
}

// ---------------------------------------------------------------------------
// 1a) A prep: fp16-convert + k-permute h into d_Ah (pair-wise, 4B writes)
// ---------------------------------------------------------------------------
__global__ __launch_bounds__(256) void aprep_kernel(const float* __restrict__ h) {
    int pi = blockIdx.x * blockDim.x + threadIdx.x;    // pair index
    if (pi >= NTOT * HIDD / 2) return;
    int row = pi >> 7;
    int q   = pi & 127;                                 // pair within row
    int k   = (q & ~7) * 2 + kpair_src(q & 7);          // source k (pair base)
    const float* src = h + (size_t)row * HIDD + k;
    ((__half2*)d_Ah)[pi] = __floats2half2_rn(src[0], src[1]);
}

// ---------------------------------------------------------------------------
// 1b) pack W^T fp16, k-permuted: d_Wh[n][k'], zero-padded n >= 928
// ---------------------------------------------------------------------------
__global__ __launch_bounds__(256) void pack_kernel(
        const float* __restrict__ Wq, const float* __restrict__ Wk,
        const float* __restrict__ Wv, const float* __restrict__ Ws) {
    int pi = blockIdx.x * blockDim.x + threadIdx.x;    // pair index
    if (pi >= PSTRIDE * HIDD / 2) return;
    int n = pi >> 7;
    int q = pi & 127;
    int k = (q & ~7) * 2 + kpair_src(q & 7);
    float v0 = 0.0f, v1 = 0.0f;
    if      (n < 232) { v0 = Wq[k * 232 + n];       v1 = Wq[(k + 1) * 232 + n]; }
    else if (n < 464) { v0 = Wk[k * 232 + n - 232]; v1 = Wk[(k + 1) * 232 + n - 232]; }
    else if (n < 696) { v0 = Wv[k * 232 + n - 464]; v1 = Wv[(k + 1) * 232 + n - 464]; }
    else if (n < 928) { v0 = Ws[k * 232 + n - 696]; v1 = Ws[(k + 1) * 232 + n - 696]; }
    ((__half2*)d_Wh)[pi] = __floats2half2_rn(v0, v1);
}

// ---------------------------------------------------------------------------
// 2) fp16 mma.sync GEMM: P[N,1024] = h[N,256] @ W[256,1024], fp16 output
// ---------------------------------------------------------------------------
__global__ __launch_bounds__(256, 2) void gemm_mma_kernel() {
    extern __shared__ __align__(16) char sm[];
    int tid  = threadIdx.x;
    int lane = tid & 31;
    int warp = tid >> 5;
    int wr = warp >> 2;          // 0..1 (M)
    int wc = warp & 3;           // 0..3 (N)
    int gid = lane >> 2;         // 0..7
    int tig = lane & 3;          // 0..3
    int brow = blockIdx.y * BM;
    int bcol = blockIdx.x * BN;

    const __half* Ag = d_Ah + (size_t)brow * HIDD;
    const __half* Bg = d_Wh + (size_t)bcol * HIDD;

    uint32_t sbase = smem_u32(sm);
    int rr0 = tid >> 2;          // 0..63 (+64 for second)
    int cc  = tid & 3;           // 16B unit within 64B row

    float c[4][4][4];
#pragma unroll
    for (int mt = 0; mt < 4; mt++)
#pragma unroll
        for (int nt = 0; nt < 4; nt++)
#pragma unroll
            for (int q = 0; q < 4; q++) c[mt][nt][q] = 0.0f;

    auto stage_in = [&](int ch) {
        uint32_t stg = sbase + (ch & 1) * 2 * STG_B;
        int kc0 = ch * BK;
#pragma unroll
        for (int t = 0; t < 2; t++) {
            int rr = rr0 + t * 64;
            uint32_t soff = (uint32_t)(rr * (RSH * 2) + cc * 16);
            cp16(stg + soff, Ag + (size_t)rr * HIDD + kc0 + cc * 8);
            cp16(stg + STG_B + soff, Bg + (size_t)rr * HIDD + kc0 + cc * 8);
        }
        asm volatile("cp.async.commit_group;");
    };

    stage_in(0);

    for (int ch = 0; ch < HIDD / BK; ch++) {
        if (ch < HIDD / BK - 1) {
            stage_in(ch + 1);
            asm volatile("cp.async.wait_group 1;");
        } else {
            asm volatile("cp.async.wait_group 0;");
        }
        __syncthreads();

        const char* As = sm + (ch & 1) * 2 * STG_B;
        const char* Bs = As + STG_B;

#pragma unroll
        for (int ks = 0; ks < 2; ks++) {
            uint32_t af[4][4];
#pragma unroll
            for (int mt = 0; mt < 4; mt++) {
                int r0 = wr * 64 + mt * 16 + gid;
                uint2 ua = *(const uint2*)(As + r0 * (RSH * 2) + ks * 32 + tig * 8);
                uint2 ub = *(const uint2*)(As + (r0 + 8) * (RSH * 2) + ks * 32 + tig * 8);
                af[mt][0] = ua.x; af[mt][2] = ua.y;
                af[mt][1] = ub.x; af[mt][3] = ub.y;
            }
            uint32_t bf[4][2];
#pragma unroll
            for (int nt = 0; nt < 4; nt++) {
                int n0 = wc * 32 + nt * 8 + gid;
                uint2 ub = *(const uint2*)(Bs + n0 * (RSH * 2) + ks * 32 + tig * 8);
                bf[nt][0] = ub.x; bf[nt][1] = ub.y;
            }
#pragma unroll
            for (int mt = 0; mt < 4; mt++)
#pragma unroll
                for (int nt = 0; nt < 4; nt++)
                    mma16816(c[mt][nt], af[mt], bf[nt]);
        }
        __syncthreads();
    }

    // Epilogue: packed fp16 stores to d_Ph, skip padded columns >= 928
#pragma unroll
    for (int mt = 0; mt < 4; mt++) {
        int r0 = brow + wr * 64 + mt * 16 + gid;
#pragma unroll
        for (int nt = 0; nt < 4; nt++) {
            int gc = bcol + wc * 32 + nt * 8 + tig * 2;
            if (gc < NPACK) {
                __half* p = d_Ph + (size_t)r0 * PSTRIDE + gc;
                *(__half2*)p = __floats2half2_rn(c[mt][nt][0], c[mt][nt][1]);
                *(__half2*)(p + 8 * PSTRIDE) = __floats2half2_rn(c[mt][nt][2], c[mt][nt][3]);
            }
        }
    }
}

// ---------------------------------------------------------------------------
// 3) warp-per-node edge attention + skip + per-node mean (half2 pairs)
//    pairs 0..57 = head 0, pairs 58..115 = head 1 (exact split at 58)
// ---------------------------------------------------------------------------
__global__ __launch_bounds__(256) void attn_kernel(const int* __restrict__ esrc) {
    int warp = (blockIdx.x * blockDim.x + threadIdx.x) >> 5;
    int lane = threadIdx.x & 31;
    if (warp >= NTOT) return;
    int i = warp;
    int is32 = d_is32;

    const __half2* Pq = (const __half2*)(d_Ph + (size_t)i * PSTRIDE);

    float2 q[4];
#pragma unroll
    for (int t = 0; t < 4; t++) {
        int p = lane + 32 * t;
        q[t] = (p < NPAIR) ? __half22float2(Pq[p]) : make_float2(0.0f, 0.0f);
    }

    int myedge = 0;
    if (lane < DEG) {
        int e = i * DEG + lane;
        myedge = is32 ? esrc[e] : esrc[2 * e];   // int64: low word
    }
    int srcs[DEG];
#pragma unroll
    for (int e = 0; e < DEG; e++) srcs[e] = __shfl_sync(0xffffffffu, myedge, e);

    const float scale = 0.09284766908852593f;    // 1/sqrt(116)
    float s0[DEG], s1[DEG];
#pragma unroll
    for (int e = 0; e < DEG; e++) {
        const __half2* Kp = (const __half2*)(d_Ph + (size_t)srcs[e] * PSTRIDE + 232);
        float a0 = 0.0f, a1 = 0.0f;
#pragma unroll
        for (int t = 0; t < 4; t++) {
            int p = lane + 32 * t;
            if (p < NPAIR) {
                float2 kv = __half22float2(Kp[p]);
                float prod = q[t].x * kv.x + q[t].y * kv.y;
                if (p < HPAIR) a0 += prod; else a1 += prod;
            }
        }
#pragma unroll
        for (int off = 16; off > 0; off >>= 1) {
            a0 += __shfl_xor_sync(0xffffffffu, a0, off);
            a1 += __shfl_xor_sync(0xffffffffu, a1, off);
        }
        s0[e] = a0 * scale;
        s1[e] = a1 * scale;
    }

    float m0 = s0[0], m1 = s1[0];
#pragma unroll
    for (int e = 1; e < DEG; e++) { m0 = fmaxf(m0, s0[e]); m1 = fmaxf(m1, s1[e]); }
    float ex0[DEG], ex1[DEG], den0 = 0.0f, den1 = 0.0f;
#pragma unroll
    for (int e = 0; e < DEG; e++) {
        ex0[e] = __expf(s0[e] - m0);
        ex1[e] = __expf(s1[e] - m1);
        den0 += ex0[e]; den1 += ex1[e];
    }
    float r0 = 1.0f / (den0 + 1e-16f);
    float r1 = 1.0f / (den1 + 1e-16f);
    float al0[DEG], al1[DEG];
#pragma unroll
    for (int e = 0; e < DEG; e++) { al0[e] = ex0[e] * r0; al1[e] = ex1[e] * r1; }

    float2 o[4];
#pragma unroll
    for (int t = 0; t < 4; t++) o[t] = make_float2(0.0f, 0.0f);
#pragma unroll
    for (int e = 0; e < DEG; e++) {
        const __half2* Vp = (const __half2*)(d_Ph + (size_t)srcs[e] * PSTRIDE + 464);
#pragma unroll
        for (int t = 0; t < 4; t++) {
            int p = lane + 32 * t;
            if (p < NPAIR) {
                float2 vv = __half22float2(Vp[p]);
                float a = (p < HPAIR) ? al0[e] : al1[e];
                o[t].x += a * vv.x;
                o[t].y += a * vv.y;
            }
        }
    }
    const __half2* Sp = (const __half2*)(d_Ph + (size_t)i * PSTRIDE + 696);
#pragma unroll
    for (int t = 0; t < 4; t++) {
        int p = lane + 32 * t;
        if (p < NPAIR) {
            float2 sv = __half22float2(Sp[p]);
            o[t].x += sv.x;
            o[t].y += sv.y;
        }
    }

    float psum = 0.0f;
#pragma unroll
    for (int t = 0; t < 4; t++) {
        int p = lane + 32 * t;
        if (p < NPAIR) psum += o[t].x + o[t].y;
    }
#pragma unroll
    for (int off = 16; off > 0; off >>= 1) psum += __shfl_xor_sync(0xffffffffu, psum, off);
    if (lane == 0) d_E[i] = psum * (1.0f / (float)DOUT);

    float2* HPp = (float2*)(d_HP + (size_t)i * DOUT);
#pragma unroll
    for (int t = 0; t < 4; t++) {
        int p = lane + 32 * t;
        if (p < NPAIR) HPp[p] = o[t];
    }
}

// ---------------------------------------------------------------------------
// 4) per-graph softmax over nodes + weighted output; writes d_out directly
// ---------------------------------------------------------------------------
__global__ __launch_bounds__(256) void finalize_kernel(float* __restrict__ out) {
    __shared__ float sh[128];
    __shared__ float alpha_sh[NODESG];
    int g = blockIdx.x;
    int tid = threadIdx.x;

    if (tid < 128) {
        float ev = (tid < NODESG) ? d_E[g * NODESG + tid] : -3.4e38f;
        sh[tid] = ev;
    }
    __syncthreads();
#pragma unroll
    for (int s = 64; s > 0; s >>= 1) {
        if (tid < s) sh[tid] = fmaxf(sh[tid], sh[tid + s]);
        __syncthreads();
    }
    float m = sh[0];
    __syncthreads();

    float ev = (tid < NODESG) ? d_E[g * NODESG + tid] : 0.0f;
    float ex = (tid < NODESG) ? __expf(ev - m) : 0.0f;
    if (tid < 128) sh[tid] = ex;
    __syncthreads();
#pragma unroll
    for (int s = 64; s > 0; s >>= 1) {
        if (tid < s) sh[tid] += sh[tid + s];
        __syncthreads();
    }
    float inv = 1.0f / sh[0];

    if (tid < NODESG) {
        float a = ex * inv;
        out[g * NODESG + tid] = a;
        alpha_sh[tid] = a;
    }
    __syncthreads();

    const float* src = d_HP + (size_t)g * (NODESG * DOUT);
    float*       dst = out + NTOT + (size_t)g * (NODESG * DOUT);
    if (tid < DOUT) {
#pragma unroll 4
        for (int n = 0; n < NODESG; n++) {
            dst[n * DOUT + tid] = alpha_sh[n] * src[n * DOUT + tid];
        }
    }
}

// ---------------------------------------------------------------------------
extern "C" void kernel_launch(void* const* d_in, const int* in_sizes, int n_in,
                              void* d_out, int out_size) {
    const float* h  = (const float*)d_in[0];
    const int*   ei = (const int*)d_in[1];
    // d_in[2] = batch_index (unused: batch = i / 116 by construction)
    const float* Wq = (const float*)d_in[3];
    const float* Wk = (const float*)d_in[4];
    const float* Wv = (const float*)d_in[5];
    const float* Ws = (const float*)d_in[6];
    float* out = (float*)d_out;

    cudaFuncSetAttribute(gemm_mma_kernel,
                         cudaFuncAttributeMaxDynamicSharedMemorySize, GEMM_SMEM);

    void* flag_ptr = nullptr;
    cudaGetSymbolAddress(&flag_ptr, d_is32);
    cudaMemsetAsync(flag_ptr, 0, sizeof(int));

    detect_kernel<<<16, 256>>>(ei);
    pack_kernel<<<(PSTRIDE * HIDD / 2 + 255) / 256, 256>>>(Wq, Wk, Wv, Ws);
    aprep_kernel<<<(NTOT * HIDD / 2 + 255) / 256, 256>>>(h);

    dim3 gg(PSTRIDE / BN, NTOT / BM);   // x=8 (ncol, fastest -> A reuse), y=464
    gemm_mma_kernel<<<gg, 256, GEMM_SMEM>>>();

    attn_kernel<<<NTOT / 8, 256>>>(ei);

    finalize_kernel<<<BGRAPH, 256>>>(out);
}

// round 9
// speedup vs baseline: 1.7269x; 1.0887x over previous
#include <cuda_runtime.h>
#include <cuda_fp16.h>
#include <math.h>
#include <stdint.h>

// Problem constants
#define NODESG   116
#define HEADS    2
#define DHEAD    116
#define HIDD     256
#define BGRAPH   512
#define NTOT     (BGRAPH * NODESG)      // 59392
#define DEG      8
#define DOUT     232
#define PSTRIDE  1024                   // padded fused output width (q|k|v|s|pad)
#define NPACK    928                    // valid columns (4*232)
#define NPAIR    116                    // half2 pairs per 232-col section
#define HPAIR    58                     // pairs in head 0

// GEMM tiling
#define BM 128
#define BN 128
#define BK 32
#define RSH 48                           // smem row stride in halves (96 B, conflict-free)
#define STG_B (BM * RSH * 2)             // bytes per operand per stage = 12288
#define NSTAGE 4
#define GEMM_SMEM (NSTAGE * 2 * STG_B)   // 98304 B

// Scratch (device globals: no allocation allowed)
__device__ __half d_Ah[(size_t)NTOT * HIDD];                  // A fp16, k-permuted
__device__ __half d_Wh[PSTRIDE * HIDD];                       // W^T padded fp16, k-permuted
__device__ __half d_Ph[(size_t)NTOT * PSTRIDE];               // fused projections (fp16)
__device__ __half d_HPh[(size_t)NTOT * DOUT];                 // h_proj (fp16)
__device__ float d_E[NTOT];                                   // per-node mean
__device__ int   d_is32;                                      // edge_index dtype flag

// k-permutation within 16-group (pair granularity):
// stored pair q (0..7) holds source k-pair base: j=q>>1; odd q -> 2j+8, even -> 2j
__device__ __forceinline__ int kpair_src(int q) {
    int j = q >> 1;
    return (q & 1) ? (2 * j + 8) : (2 * j);
}

// ---------------------------------------------------------------------------
// helpers
// ---------------------------------------------------------------------------
__device__ __forceinline__ void mma16816(float* c, const uint32_t* a, const uint32_t* b) {
    asm volatile(
        "mma.sync.aligned.m16n8k16.row.col.f32.f16.f16.f32 "
        "{%0,%1,%2,%3},{%4,%5,%6,%7},{%8,%9},{%0,%1,%2,%3};"
        : "+f"(c[0]), "+f"(c[1]), "+f"(c[2]), "+f"(c[3])
        : "r"(a[0]), "r"(a[1]), "r"(a[2]), "r"(a[3]), "r"(b[0]), "r"(b[1]));
}
__device__ __forceinline__ uint32_t smem_u32(const void* p) {
    uint32_t a;
    asm("{ .reg .u64 t; cvta.to.shared.u64 t, %1; cvt.u32.u64 %0, t; }" : "=r"(a) : "l"(p));
    return a;
}
__device__ __forceinline__ void cp16(uint32_t dst, const void* src) {
    asm volatile("cp.async.cg.shared.global [%0], [%1], 16;" :: "r"(dst), "l"(src));
}

// ---------------------------------------------------------------------------
// 0) edge_index dtype detection: int64 little-endian => all odd int32 words 0
// ---------------------------------------------------------------------------
__global__ void detect_kernel(const int* __restrict__ ei) {
    int j = blockIdx.x * blockDim.x + threadIdx.x;
    if (j < 4096) {
        if (ei[2 * j + 1] != 0) atomicOr(&d_is32, 1);
    }
}

// ---------------------------------------------------------------------------
// 1a) A prep: fp16-convert + k-permute h into d_Ah; 1 thread = 16-float group
// ---------------------------------------------------------------------------
__global__ __launch_bounds__(256) void aprep_kernel(const float* __restrict__ h) {
    int gi = blockIdx.x * blockDim.x + threadIdx.x;    // 16-float group index
    if (gi >= NTOT * HIDD / 16) return;
    const float4* src = (const float4*)(h + (size_t)gi * 16);
    float4 v0 = src[0], v1 = src[1], v2 = src[2], v3 = src[3];
    float s[16] = {v0.x, v0.y, v0.z, v0.w, v1.x, v1.y, v1.z, v1.w,
                   v2.x, v2.y, v2.z, v2.w, v3.x, v3.y, v3.z, v3.w};
    __half2 o[8];
#pragma unroll
    for (int q = 0; q < 8; q++) {
        int k = kpair_src(q);
        o[q] = __floats2half2_rn(s[k], s[k + 1]);
    }
    uint4* dst = (uint4*)(d_Ah + (size_t)gi * 16);
    dst[0] = *(uint4*)&o[0];
    dst[1] = *(uint4*)&o[4];
}

// ---------------------------------------------------------------------------
// 1b) pack W^T fp16, k-permuted: d_Wh[n][k'], zero-padded n >= 928
// ---------------------------------------------------------------------------
__global__ __launch_bounds__(256) void pack_kernel(
        const float* __restrict__ Wq, const float* __restrict__ Wk,
        const float* __restrict__ Wv, const float* __restrict__ Ws) {
    int pi = blockIdx.x * blockDim.x + threadIdx.x;    // pair index
    if (pi >= PSTRIDE * HIDD / 2) return;
    int n = pi >> 7;
    int q = pi & 127;
    int k = (q & ~7) * 2 + kpair_src(q & 7);
    float v0 = 0.0f, v1 = 0.0f;
    if      (n < 232) { v0 = Wq[k * 232 + n];       v1 = Wq[(k + 1) * 232 + n]; }
    else if (n < 464) { v0 = Wk[k * 232 + n - 232]; v1 = Wk[(k + 1) * 232 + n - 232]; }
    else if (n < 696) { v0 = Wv[k * 232 + n - 464]; v1 = Wv[(k + 1) * 232 + n - 464]; }
    else if (n < 928) { v0 = Ws[k * 232 + n - 696]; v1 = Ws[(k + 1) * 232 + n - 696]; }
    ((__half2*)d_Wh)[pi] = __floats2half2_rn(v0, v1);
}

// ---------------------------------------------------------------------------
// 2) fp16 mma.sync GEMM: P[N,1024] = h[N,256] @ W[256,1024], fp16 output
//    4-stage cp.async ring, prefetch distance 2, one __syncthreads per chunk.
// ---------------------------------------------------------------------------
__global__ __launch_bounds__(256, 2) void gemm_mma_kernel() {
    extern __shared__ __align__(16) char sm[];
    int tid  = threadIdx.x;
    int lane = tid & 31;
    int warp = tid >> 5;
    int wr = warp >> 2;          // 0..1 (M)
    int wc = warp & 3;           // 0..3 (N)
    int gid = lane >> 2;         // 0..7
    int tig = lane & 3;          // 0..3
    int brow = blockIdx.y * BM;
    int bcol = blockIdx.x * BN;

    const __half* Ag = d_Ah + (size_t)brow * HIDD;
    const __half* Bg = d_Wh + (size_t)bcol * HIDD;

    uint32_t sbase = smem_u32(sm);
    int rr0 = tid >> 2;          // 0..63 (+64 for second)
    int cc  = tid & 3;           // 16B unit within 64B row

    float c[4][4][4];
#pragma unroll
    for (int mt = 0; mt < 4; mt++)
#pragma unroll
        for (int nt = 0; nt < 4; nt++)
#pragma unroll
            for (int q = 0; q < 4; q++) c[mt][nt][q] = 0.0f;

    auto stage_in = [&](int ch) {
        uint32_t stg = sbase + (ch & (NSTAGE - 1)) * 2 * STG_B;
        int kc0 = ch * BK;
#pragma unroll
        for (int t = 0; t < 2; t++) {
            int rr = rr0 + t * 64;
            uint32_t soff = (uint32_t)(rr * (RSH * 2) + cc * 16);
            cp16(stg + soff, Ag + (size_t)rr * HIDD + kc0 + cc * 8);
            cp16(stg + STG_B + soff, Bg + (size_t)rr * HIDD + kc0 + cc * 8);
        }
        asm volatile("cp.async.commit_group;");
    };

    stage_in(0);
    stage_in(1);

    const int NCH = HIDD / BK;   // 8
    for (int ch = 0; ch < NCH; ch++) {
        if (ch + 2 < NCH) {
            stage_in(ch + 2);
            asm volatile("cp.async.wait_group 2;");
        } else if (ch + 1 < NCH) {
            asm volatile("cp.async.wait_group 1;");
        } else {
            asm volatile("cp.async.wait_group 0;");
        }
        __syncthreads();

        const char* As = sm + (ch & (NSTAGE - 1)) * 2 * STG_B;
        const char* Bs = As + STG_B;

#pragma unroll
        for (int ks = 0; ks < 2; ks++) {
            uint32_t af[4][4];
#pragma unroll
            for (int mt = 0; mt < 4; mt++) {
                int r0 = wr * 64 + mt * 16 + gid;
                uint2 ua = *(const uint2*)(As + r0 * (RSH * 2) + ks * 32 + tig * 8);
                uint2 ub = *(const uint2*)(As + (r0 + 8) * (RSH * 2) + ks * 32 + tig * 8);
                af[mt][0] = ua.x; af[mt][2] = ua.y;
                af[mt][1] = ub.x; af[mt][3] = ub.y;
            }
            uint32_t bf[4][2];
#pragma unroll
            for (int nt = 0; nt < 4; nt++) {
                int n0 = wc * 32 + nt * 8 + gid;
                uint2 ub = *(const uint2*)(Bs + n0 * (RSH * 2) + ks * 32 + tig * 8);
                bf[nt][0] = ub.x; bf[nt][1] = ub.y;
            }
#pragma unroll
            for (int mt = 0; mt < 4; mt++)
#pragma unroll
                for (int nt = 0; nt < 4; nt++)
                    mma16816(c[mt][nt], af[mt], bf[nt]);
        }
    }

    // Epilogue: packed fp16 stores to d_Ph, skip padded columns >= 928
#pragma unroll
    for (int mt = 0; mt < 4; mt++) {
        int r0 = brow + wr * 64 + mt * 16 + gid;
#pragma unroll
        for (int nt = 0; nt < 4; nt++) {
            int gc = bcol + wc * 32 + nt * 8 + tig * 2;
            if (gc < NPACK) {
                __half* p = d_Ph + (size_t)r0 * PSTRIDE + gc;
                *(__half2*)p = __floats2half2_rn(c[mt][nt][0], c[mt][nt][1]);
                *(__half2*)(p + 8 * PSTRIDE) = __floats2half2_rn(c[mt][nt][2], c[mt][nt][3]);
            }
        }
    }
}

// ---------------------------------------------------------------------------
// 3) warp-per-node edge attention + skip + per-node mean (half2 pairs)
//    pairs 0..57 = head 0, pairs 58..115 = head 1 (exact split at 58)
// ---------------------------------------------------------------------------
__global__ __launch_bounds__(256) void attn_kernel(const int* __restrict__ esrc) {
    int warp = (blockIdx.x * blockDim.x + threadIdx.x) >> 5;
    int lane = threadIdx.x & 31;
    if (warp >= NTOT) return;
    int i = warp;
    int is32 = d_is32;

    const __half2* Pq = (const __half2*)(d_Ph + (size_t)i * PSTRIDE);

    float2 q[4];
#pragma unroll
    for (int t = 0; t < 4; t++) {
        int p = lane + 32 * t;
        q[t] = (p < NPAIR) ? __half22float2(Pq[p]) : make_float2(0.0f, 0.0f);
    }

    int myedge = 0;
    if (lane < DEG) {
        int e = i * DEG + lane;
        myedge = is32 ? esrc[e] : esrc[2 * e];   // int64: low word
    }
    int srcs[DEG];
#pragma unroll
    for (int e = 0; e < DEG; e++) srcs[e] = __shfl_sync(0xffffffffu, myedge, e);

    const float scale = 0.09284766908852593f;    // 1/sqrt(116)
    float s0[DEG], s1[DEG];
#pragma unroll
    for (int e = 0; e < DEG; e++) {
        const __half2* Kp = (const __half2*)(d_Ph + (size_t)srcs[e] * PSTRIDE + 232);
        float a0 = 0.0f, a1 = 0.0f;
#pragma unroll
        for (int t = 0; t < 4; t++) {
            int p = lane + 32 * t;
            if (p < NPAIR) {
                float2 kv = __half22float2(Kp[p]);
                float prod = q[t].x * kv.x + q[t].y * kv.y;
                if (p < HPAIR) a0 += prod; else a1 += prod;
            }
        }
#pragma unroll
        for (int off = 16; off > 0; off >>= 1) {
            a0 += __shfl_xor_sync(0xffffffffu, a0, off);
            a1 += __shfl_xor_sync(0xffffffffu, a1, off);
        }
        s0[e] = a0 * scale;
        s1[e] = a1 * scale;
    }

    float m0 = s0[0], m1 = s1[0];
#pragma unroll
    for (int e = 1; e < DEG; e++) { m0 = fmaxf(m0, s0[e]); m1 = fmaxf(m1, s1[e]); }
    float ex0[DEG], ex1[DEG], den0 = 0.0f, den1 = 0.0f;
#pragma unroll
    for (int e = 0; e < DEG; e++) {
        ex0[e] = __expf(s0[e] - m0);
        ex1[e] = __expf(s1[e] - m1);
        den0 += ex0[e]; den1 += ex1[e];
    }
    float r0 = 1.0f / (den0 + 1e-16f);
    float r1 = 1.0f / (den1 + 1e-16f);
    float al0[DEG], al1[DEG];
#pragma unroll
    for (int e = 0; e < DEG; e++) { al0[e] = ex0[e] * r0; al1[e] = ex1[e] * r1; }

    float2 o[4];
#pragma unroll
    for (int t = 0; t < 4; t++) o[t] = make_float2(0.0f, 0.0f);
#pragma unroll
    for (int e = 0; e < DEG; e++) {
        const __half2* Vp = (const __half2*)(d_Ph + (size_t)srcs[e] * PSTRIDE + 464);
#pragma unroll
        for (int t = 0; t < 4; t++) {
            int p = lane + 32 * t;
            if (p < NPAIR) {
                float2 vv = __half22float2(Vp[p]);
                float a = (p < HPAIR) ? al0[e] : al1[e];
                o[t].x += a * vv.x;
                o[t].y += a * vv.y;
            }
        }
    }
    const __half2* Sp = (const __half2*)(d_Ph + (size_t)i * PSTRIDE + 696);
#pragma unroll
    for (int t = 0; t < 4; t++) {
        int p = lane + 32 * t;
        if (p < NPAIR) {
            float2 sv = __half22float2(Sp[p]);
            o[t].x += sv.x;
            o[t].y += sv.y;
        }
    }

    float psum = 0.0f;
#pragma unroll
    for (int t = 0; t < 4; t++) {
        int p = lane + 32 * t;
        if (p < NPAIR) psum += o[t].x + o[t].y;
    }
#pragma unroll
    for (int off = 16; off > 0; off >>= 1) psum += __shfl_xor_sync(0xffffffffu, psum, off);
    if (lane == 0) d_E[i] = psum * (1.0f / (float)DOUT);

    __half2* HPp = (__half2*)(d_HPh + (size_t)i * DOUT);
#pragma unroll
    for (int t = 0; t < 4; t++) {
        int p = lane + 32 * t;
        if (p < NPAIR) HPp[p] = __floats2half2_rn(o[t].x, o[t].y);
    }
}

// ---------------------------------------------------------------------------
// 4) per-graph softmax over nodes + weighted output; writes d_out directly
// ---------------------------------------------------------------------------
__global__ __launch_bounds__(256) void finalize_kernel(float* __restrict__ out) {
    __shared__ float sh[128];
    __shared__ float alpha_sh[NODESG];
    int g = blockIdx.x;
    int tid = threadIdx.x;

    if (tid < 128) {
        float ev = (tid < NODESG) ? d_E[g * NODESG + tid] : -3.4e38f;
        sh[tid] = ev;
    }
    __syncthreads();
#pragma unroll
    for (int s = 64; s > 0; s >>= 1) {
        if (tid < s) sh[tid] = fmaxf(sh[tid], sh[tid + s]);
        __syncthreads();
    }
    float m = sh[0];
    __syncthreads();

    float ev = (tid < NODESG) ? d_E[g * NODESG + tid] : 0.0f;
    float ex = (tid < NODESG) ? __expf(ev - m) : 0.0f;
    if (tid < 128) sh[tid] = ex;
    __syncthreads();
#pragma unroll
    for (int s = 64; s > 0; s >>= 1) {
        if (tid < s) sh[tid] += sh[tid + s];
        __syncthreads();
    }
    float inv = 1.0f / sh[0];

    if (tid < NODESG) {
        float a = ex * inv;
        out[g * NODESG + tid] = a;
        alpha_sh[tid] = a;
    }
    __syncthreads();

    const __half* src = d_HPh + (size_t)g * (NODESG * DOUT);
    float*        dst = out + NTOT + (size_t)g * (NODESG * DOUT);
    if (tid < DOUT) {
#pragma unroll 4
        for (int n = 0; n < NODESG; n++) {
            dst[n * DOUT + tid] = alpha_sh[n] * __half2float(src[n * DOUT + tid]);
        }
    }
}

// ---------------------------------------------------------------------------
extern "C" void kernel_launch(void* const* d_in, const int* in_sizes, int n_in,
                              void* d_out, int out_size) {
    const float* h  = (const float*)d_in[0];
    const int*   ei = (const int*)d_in[1];
    // d_in[2] = batch_index (unused: batch = i / 116 by construction)
    const float* Wq = (const float*)d_in[3];
    const float* Wk = (const float*)d_in[4];
    const float* Wv = (const float*)d_in[5];
    const float* Ws = (const float*)d_in[6];
    float* out = (float*)d_out;

    cudaFuncSetAttribute(gemm_mma_kernel,
                         cudaFuncAttributeMaxDynamicSharedMemorySize, GEMM_SMEM);

    void* flag_ptr = nullptr;
    cudaGetSymbolAddress(&flag_ptr, d_is32);
    cudaMemsetAsync(flag_ptr, 0, sizeof(int));

    detect_kernel<<<16, 256>>>(ei);
    pack_kernel<<<(PSTRIDE * HIDD / 2 + 255) / 256, 256>>>(Wq, Wk, Wv, Ws);
    aprep_kernel<<<(NTOT * HIDD / 16 + 255) / 256, 256>>>(h);

    dim3 gg(PSTRIDE / BN, NTOT / BM);   // x=8 (ncol, fastest -> A reuse), y=464
    gemm_mma_kernel<<<gg, 256, GEMM_SMEM>>>();

    attn_kernel<<<NTOT / 8, 256>>>(ei);

    finalize_kernel<<<BGRAPH, 256>>>(out);
}